// round 14
// baseline (speedup 1.0000x reference)
#include <cuda_runtime.h>
#include <math.h>

#define D 128
#define NRBF 20
#define NNODES 25000
#define NEDGES 250000
#define NGRAPHS 512

// ---------------- scratch (device globals; no allocation) ----------------
__device__ float g_state0[NNODES * D];
__device__ float g_state_acc[NNODES * D];
__device__ float g_state_vec[NNODES * 3 * D];
__device__ float g_phi[NNODES * 2 * D];         // per-node phi cols 128..383 (m2|m3)
__device__ float g_UV[NNODES * D];
__device__ float g_Vn[NNODES * D];
__device__ float g_graph[NGRAPHS * D];

typedef unsigned long long u64;

__device__ __forceinline__ float silu_f(float x) {
    return x / (1.0f + __expf(-x));
}

__device__ __forceinline__ u64 pk2(float lo, float hi) {
    u64 r;
    asm("mov.b64 %0, {%1, %2};" : "=l"(r) : "r"(__float_as_uint(lo)), "r"(__float_as_uint(hi)));
    return r;
}
__device__ __forceinline__ float2 upk2(u64 v) {
    unsigned lo, hi;
    asm("mov.b64 {%0, %1}, %2;" : "=r"(lo), "=r"(hi) : "l"(v));
    return make_float2(__uint_as_float(lo), __uint_as_float(hi));
}
__device__ __forceinline__ void fma2(u64& acc, u64 a, u64 b) {
    asm("fma.rn.f32x2 %0, %1, %2, %0;" : "+l"(acc) : "l"(a), "l"(b));
}

// ---------------- init ----------------
__global__ void init_kernel(const float* __restrict__ emb, const int* __restrict__ atype) {
    int stride = gridDim.x * blockDim.x;
    int total = NNODES * 3 * D;
    for (int idx = blockIdx.x * blockDim.x + threadIdx.x; idx < total; idx += stride) {
        g_state_vec[idx] = 0.0f;
        if (idx < NNODES * D) {
            int n = idx >> 7;
            int j = idx & 127;
            g_state0[idx] = emb[atype[n] * D + j];
            g_state_acc[idx] = 0.0f;
        }
        if (idx < NGRAPHS * D) g_graph[idx] = 0.0f;
    }
}

// ---------------- per-node phi MLP ----------------
__global__ __launch_bounds__(128) void node_phi_kernel(
    const float* __restrict__ phi_W1, const float* __restrict__ phi_b1,
    const float* __restrict__ phi_W2, const float* __restrict__ phi_b2)
{
    __shared__ float sA[64][132];
    __shared__ float sW[32][132];
    const int t = threadIdx.x;
    const int n0 = blockIdx.x * 64;

    for (int k = t; k < 64 * 32; k += 128) {
        int row = k >> 5, c4 = k & 31;
        int n = n0 + row;
        float4 v = make_float4(0.f, 0.f, 0.f, 0.f);
        if (n < NNODES) v = ((const float4*)(g_state0 + (size_t)n * D))[c4];
        *(float4*)(&sA[row][c4 * 4]) = v;
    }

    const int ty = t >> 4;
    const int tx = t & 15;
    const int r0 = ty * 8, c0 = tx * 8;

    u64 acc[8][4];
    #pragma unroll
    for (int i = 0; i < 8; i++)
        #pragma unroll
        for (int j = 0; j < 4; j++) acc[i][j] = 0ull;

    for (int k0 = 0; k0 < D; k0 += 32) {
        __syncthreads();
        for (int k = t; k < 32 * 32; k += 128) {
            int row = k >> 5, c4 = k & 31;
            *(float4*)(&sW[row][c4 * 4]) = __ldg((const float4*)(phi_W1 + (k0 + row) * D + c4 * 4));
        }
        __syncthreads();
        for (int kk = 0; kk < 32; kk++) {
            u64 ad[8];
            #pragma unroll
            for (int i = 0; i < 8; i++) {
                float a = sA[r0 + i][k0 + kk];
                ad[i] = pk2(a, a);
            }
            ulonglong2 q0 = *(const ulonglong2*)(&sW[kk][c0]);
            ulonglong2 q1 = *(const ulonglong2*)(&sW[kk][c0 + 4]);
            u64 bp[4] = {q0.x, q0.y, q1.x, q1.y};
            #pragma unroll
            for (int i = 0; i < 8; i++)
                #pragma unroll
                for (int j = 0; j < 4; j++) fma2(acc[i][j], ad[i], bp[j]);
        }
    }
    __syncthreads();
    #pragma unroll
    for (int j = 0; j < 4; j++) {
        float bias0 = __ldg(&phi_b1[c0 + 2 * j]);
        float bias1 = __ldg(&phi_b1[c0 + 2 * j + 1]);
        #pragma unroll
        for (int i = 0; i < 8; i++) {
            float2 v = upk2(acc[i][j]);
            sA[r0 + i][c0 + 2 * j] = silu_f(v.x + bias0);
            sA[r0 + i][c0 + 2 * j + 1] = silu_f(v.y + bias1);
        }
    }
    __syncthreads();

    #pragma unroll 1
    for (int half = 0; half < 2; half++) {
        const int cb = D + half * D;
        u64 acc2[8][4];
        #pragma unroll
        for (int i = 0; i < 8; i++)
            #pragma unroll
            for (int j = 0; j < 4; j++) acc2[i][j] = 0ull;

        for (int k0 = 0; k0 < D; k0 += 32) {
            __syncthreads();
            for (int k = t; k < 32 * 32; k += 128) {
                int row = k >> 5, c4 = k & 31;
                *(float4*)(&sW[row][c4 * 4]) = __ldg((const float4*)(phi_W2 + (k0 + row) * 384 + cb + c4 * 4));
            }
            __syncthreads();
            for (int kk = 0; kk < 32; kk++) {
                u64 ad[8];
                #pragma unroll
                for (int i = 0; i < 8; i++) {
                    float a = sA[r0 + i][k0 + kk];
                    ad[i] = pk2(a, a);
                }
                ulonglong2 q0 = *(const ulonglong2*)(&sW[kk][c0]);
                ulonglong2 q1 = *(const ulonglong2*)(&sW[kk][c0 + 4]);
                u64 bp[4] = {q0.x, q0.y, q1.x, q1.y};
                #pragma unroll
                for (int i = 0; i < 8; i++)
                    #pragma unroll
                    for (int j = 0; j < 4; j++) fma2(acc2[i][j], ad[i], bp[j]);
            }
        }

        #pragma unroll
        for (int i = 0; i < 8; i++) {
            int n = n0 + r0 + i;
            if (n < NNODES) {
                float2 p0 = upk2(acc2[i][0]);
                float2 p1 = upk2(acc2[i][1]);
                float2 p2 = upk2(acc2[i][2]);
                float2 p3 = upk2(acc2[i][3]);
                float4* dst = (float4*)(g_phi + (size_t)n * 256 + half * D + c0);
                dst[0] = make_float4(p0.x + __ldg(&phi_b2[cb + c0 + 0]),
                                     p0.y + __ldg(&phi_b2[cb + c0 + 1]),
                                     p1.x + __ldg(&phi_b2[cb + c0 + 2]),
                                     p1.y + __ldg(&phi_b2[cb + c0 + 3]));
                dst[1] = make_float4(p2.x + __ldg(&phi_b2[cb + c0 + 4]),
                                     p2.y + __ldg(&phi_b2[cb + c0 + 5]),
                                     p3.x + __ldg(&phi_b2[cb + c0 + 6]),
                                     p3.y + __ldg(&phi_b2[cb + c0 + 7]));
            }
        }
    }
}

// ---------------- edge kernel: smem-staged filter GEMM + gather + scatter ----------------
// 64 edges / block, 256 threads = 8 edge-slots x 32 col-groups; thread loops 8 edges.
__global__ __launch_bounds__(256) void edge_kernel(
    const float* __restrict__ edge_vec,
    const float* __restrict__ filt_W, const float* __restrict__ filt_b,
    const int* __restrict__ node_from, const int* __restrict__ node_to)
{
    __shared__ float sW[20][264];
    __shared__ float sWb[256];
    __shared__ float sRbf[64][22];
    __shared__ float sFc[64];
    __shared__ float sFcInv[64];
    __shared__ float sDist[64];
    __shared__ float sNorm[64][4];
    __shared__ int   sFrom[64];
    __shared__ int   sTo[64];

    const int t = threadIdx.x;
    const int e0 = blockIdx.x * 64;
    const float PI = 3.14159265358979323846f;

    for (int k = t; k < 20 * 64; k += 256) {
        int row = k >> 6, c4 = k & 63;
        *(float4*)(&sW[row][c4 * 4]) = __ldg((const float4*)(filt_W + row * 384 + 128 + c4 * 4));
    }
    if (t < 64) *(float4*)(&sWb[t * 4]) = __ldg((const float4*)(filt_b + 128 + t * 4));

    if (t < 64) {
        int e = e0 + t;
        float d = 1.f, fcv = 0.f, nx = 0.f, ny = 0.f, nz = 0.f;
        int f = 0, to = 0;
        if (e < NEDGES) {
            float x = edge_vec[3 * e + 0];
            float y = edge_vec[3 * e + 1];
            float z = edge_vec[3 * e + 2];
            d = sqrtf(x * x + y * y + z * z);
            float inv = 1.0f / d;
            fcv = (d < 10.0f) ? 0.5f * (__cosf(PI * d * 0.1f) + 1.0f) : 0.0f;
            nx = x * inv; ny = y * inv; nz = z * inv;
            f = node_from[e]; to = node_to[e];
        }
        sDist[t] = d;
        sFc[t] = fcv;
        sFcInv[t] = fcv / d;
        sNorm[t][0] = nx; sNorm[t][1] = ny; sNorm[t][2] = nz;
        sFrom[t] = f; sTo[t] = to;
    }
    __syncthreads();
    for (int idx = t; idx < 64 * NRBF; idx += 256) {
        int le = idx & 63;
        int r = idx >> 6;
        sRbf[le][r] = __sinf((float)(r + 1) * PI * sDist[le] * 0.1f) * sFcInv[le];
    }
    __syncthreads();

    const int es = t >> 5;            // edge slot 0..7 (constant within warp)
    const int c0 = (t & 31) * 8;      // col group 0..248

    ulonglong2 qb0 = *(const ulonglong2*)(&sWb[c0]);
    ulonglong2 qb1 = *(const ulonglong2*)(&sWb[c0 + 4]);
    u64 wb[4] = {qb0.x, qb0.y, qb1.x, qb1.y};

    u64 acc[8][4];
    #pragma unroll
    for (int m = 0; m < 8; m++) {
        float fc = sFc[es + 8 * m];
        u64 fp = pk2(fc, fc);
        #pragma unroll
        for (int j = 0; j < 4; j++) {
            acc[m][j] = 0ull;
            fma2(acc[m][j], fp, wb[j]);
        }
    }

    // filter GEMM: W_out = rbf_fc @ filt_W + fc*b  (8 edges per thread)
    #pragma unroll
    for (int r = 0; r < NRBF; r++) {
        ulonglong2 q0 = *(const ulonglong2*)(&sW[r][c0]);
        ulonglong2 q1 = *(const ulonglong2*)(&sW[r][c0 + 4]);
        u64 b[4] = {q0.x, q0.y, q1.x, q1.y};
        #pragma unroll
        for (int m = 0; m < 8; m++) {
            float a = sRbf[es + 8 * m][r];   // broadcast within warp
            u64 av = pk2(a, a);
            #pragma unroll
            for (int j = 0; j < 4; j++) fma2(acc[m][j], av, b[j]);
        }
    }

    #pragma unroll 1
    for (int m = 0; m < 8; m++) {
        int le = es + 8 * m;
        int e = e0 + le;
        if (e >= NEDGES) continue;
        const float4* ph = (const float4*)(g_phi + (size_t)sFrom[le] * 256 + c0);
        float4 p0 = ph[0];
        float4 p1 = ph[1];
        float2 w0 = upk2(acc[m][0]);
        float2 w1 = upk2(acc[m][1]);
        float2 w2 = upk2(acc[m][2]);
        float2 w3 = upk2(acc[m][3]);
        float pf[8];
        pf[0] = p0.x * w0.x; pf[1] = p0.y * w0.y; pf[2] = p0.z * w1.x; pf[3] = p0.w * w1.y;
        pf[4] = p1.x * w2.x; pf[5] = p1.y * w2.y; pf[6] = p1.z * w3.x; pf[7] = p1.w * w3.y;

        const int to = sTo[le];
        if (c0 < 128) {
            float4* dst = (float4*)(g_state_acc + (size_t)to * D + c0);
            atomicAdd(dst,     make_float4(pf[0], pf[1], pf[2], pf[3]));
            atomicAdd(dst + 1, make_float4(pf[4], pf[5], pf[6], pf[7]));
        } else {
            const int jj = c0 - 128;
            float n0 = sNorm[le][0], n1 = sNorm[le][1], n2 = sNorm[le][2];
            float* base = g_state_vec + (size_t)to * (3 * D) + jj;
            atomicAdd((float4*)(base),             make_float4(n0 * pf[0], n0 * pf[1], n0 * pf[2], n0 * pf[3]));
            atomicAdd((float4*)(base + 4),         make_float4(n0 * pf[4], n0 * pf[5], n0 * pf[6], n0 * pf[7]));
            atomicAdd((float4*)(base + D),         make_float4(n1 * pf[0], n1 * pf[1], n1 * pf[2], n1 * pf[3]));
            atomicAdd((float4*)(base + D + 4),     make_float4(n1 * pf[4], n1 * pf[5], n1 * pf[6], n1 * pf[7]));
            atomicAdd((float4*)(base + 2 * D),     make_float4(n2 * pf[0], n2 * pf[1], n2 * pf[2], n2 * pf[3]));
            atomicAdd((float4*)(base + 2 * D + 4), make_float4(n2 * pf[4], n2 * pf[5], n2 * pf[6], n2 * pf[7]));
        }
    }
}

// ---------------- fused UV kernel: Up/Vp GEMM + UV/Vn reduce ----------------
// 16 nodes / block, 256 threads, 4 blocks/SM target (64-reg budget experiment).
__global__ __launch_bounds__(256, 4) void uv_kernel(
    const float* __restrict__ U_W, const float* __restrict__ V_W)
{
    __shared__ float sAt[16][68];
    __shared__ float sU[16][132];
    __shared__ float sV[16][132];
    const int t = threadIdx.x;
    const int nb0 = blockIdx.x * 16;
    const int rb = nb0 * 3;
    const int NR = NNODES * 3;

    const int ng = t >> 5;
    const int c0 = (t & 31) * 4;

    u64 acc_u[2][3][2], acc_v[2][3][2];
    #pragma unroll
    for (int m = 0; m < 2; m++)
        #pragma unroll
        for (int c = 0; c < 3; c++)
            #pragma unroll
            for (int j = 0; j < 2; j++) { acc_u[m][c][j] = 0ull; acc_v[m][c][j] = 0ull; }

    for (int k0 = 0; k0 < D; k0 += 16) {
        __syncthreads();
        for (int idx = t; idx < 48 * 16; idx += 256) {
            int row = idx >> 4;
            int k = idx & 15;
            int r = rb + row;
            float v = (r < NR) ? g_state_vec[(size_t)r * D + k0 + k] : 0.f;
            int nl = row / 3, comp = row - nl * 3;
            sAt[k][nl * 4 + comp] = v;
        }
        for (int k = t; k < 16 * 32; k += 256) {
            int row = k >> 5, c4 = k & 31;
            *(float4*)(&sU[row][c4 * 4]) = __ldg((const float4*)(U_W + (k0 + row) * D + c4 * 4));
            *(float4*)(&sV[row][c4 * 4]) = __ldg((const float4*)(V_W + (k0 + row) * D + c4 * 4));
        }
        __syncthreads();
        #pragma unroll
        for (int kk = 0; kk < 16; kk++) {
            ulonglong2 qu = *(const ulonglong2*)(&sU[kk][c0]);
            ulonglong2 qv = *(const ulonglong2*)(&sV[kk][c0]);
            u64 bu[2] = {qu.x, qu.y};
            u64 bv[2] = {qv.x, qv.y};
            #pragma unroll
            for (int m = 0; m < 2; m++) {
                float4 a = *(const float4*)(&sAt[kk][(ng + 8 * m) * 4]);
                u64 d0 = pk2(a.x, a.x), d1 = pk2(a.y, a.y), d2 = pk2(a.z, a.z);
                #pragma unroll
                for (int j = 0; j < 2; j++) {
                    fma2(acc_u[m][0][j], d0, bu[j]);
                    fma2(acc_u[m][1][j], d1, bu[j]);
                    fma2(acc_u[m][2][j], d2, bu[j]);
                    fma2(acc_v[m][0][j], d0, bv[j]);
                    fma2(acc_v[m][1][j], d1, bv[j]);
                    fma2(acc_v[m][2][j], d2, bv[j]);
                }
            }
        }
    }

    #pragma unroll
    for (int m = 0; m < 2; m++) {
        int node = nb0 + ng + 8 * m;
        if (node < NNODES) {
            float uvv[4], vnv[4];
            #pragma unroll
            for (int j = 0; j < 2; j++) {
                float2 U0 = upk2(acc_u[m][0][j]), U1 = upk2(acc_u[m][1][j]), U2 = upk2(acc_u[m][2][j]);
                float2 V0 = upk2(acc_v[m][0][j]), V1 = upk2(acc_v[m][1][j]), V2 = upk2(acc_v[m][2][j]);
                uvv[2 * j]     = U0.x * V0.x + U1.x * V1.x + U2.x * V2.x;
                uvv[2 * j + 1] = U0.y * V0.y + U1.y * V1.y + U2.y * V2.y;
                vnv[2 * j]     = sqrtf(V0.x * V0.x + V1.x * V1.x + V2.x * V2.x);
                vnv[2 * j + 1] = sqrtf(V0.y * V0.y + V1.y * V1.y + V2.y * V2.y);
            }
            *(float4*)(g_UV + (size_t)node * D + c0) = make_float4(uvv[0], uvv[1], uvv[2], uvv[3]);
            *(float4*)(g_Vn + (size_t)node * D + c0) = make_float4(vnv[0], vnv[1], vnv[2], vnv[3]);
        }
    }
}

// ---------------- node update MLP + segment-sum (R8 proven version) ----------------
__global__ __launch_bounds__(128) void update_kernel(
    const float* __restrict__ upd_W1, const float* __restrict__ upd_b1,
    const float* __restrict__ upd_W2, const float* __restrict__ upd_b2,
    const int* __restrict__ node_graph_index)
{
    __shared__ float sA[32][260];
    __shared__ float sW[32][264];
    const int t = threadIdx.x;
    const int n0 = blockIdx.x * 32;

    for (int k = t; k < 32 * 64; k += 128) {
        int row = k >> 6, c4 = k & 63;
        int n = n0 + row;
        float4 v = make_float4(0.f, 0.f, 0.f, 0.f);
        if (n < NNODES) {
            if (c4 < 32) {
                v = ((const float4*)(g_Vn + (size_t)n * D))[c4];
            } else {
                float4 s0 = ((const float4*)(g_state0 + (size_t)n * D))[c4 - 32];
                float4 s1 = ((const float4*)(g_state_acc + (size_t)n * D))[c4 - 32];
                v = make_float4(s0.x + s1.x, s0.y + s1.y, s0.z + s1.z, s0.w + s1.w);
            }
        }
        *(float4*)(&sA[row][c4 * 4]) = v;
    }

    const int ty = t >> 4;
    const int tx = t & 15;
    const int r0 = ty * 4, c0 = tx * 8;

    u64 acc[4][4];
    #pragma unroll
    for (int i = 0; i < 4; i++)
        #pragma unroll
        for (int j = 0; j < 4; j++) acc[i][j] = 0ull;

    for (int k0 = 0; k0 < 2 * D; k0 += 32) {
        __syncthreads();
        for (int k = t; k < 32 * 32; k += 128) {
            int row = k >> 5, c4 = k & 31;
            *(float4*)(&sW[row][c4 * 4]) = __ldg((const float4*)(upd_W1 + (k0 + row) * D + c4 * 4));
        }
        __syncthreads();
        for (int kk = 0; kk < 32; kk++) {
            u64 ad[4];
            #pragma unroll
            for (int i = 0; i < 4; i++) {
                float a = sA[r0 + i][k0 + kk];
                ad[i] = pk2(a, a);
            }
            ulonglong2 q0 = *(const ulonglong2*)(&sW[kk][c0]);
            ulonglong2 q1 = *(const ulonglong2*)(&sW[kk][c0 + 4]);
            u64 bp[4] = {q0.x, q0.y, q1.x, q1.y};
            #pragma unroll
            for (int i = 0; i < 4; i++)
                #pragma unroll
                for (int j = 0; j < 4; j++) fma2(acc[i][j], ad[i], bp[j]);
        }
    }
    __syncthreads();
    #pragma unroll
    for (int j = 0; j < 4; j++) {
        float bias0 = __ldg(&upd_b1[c0 + 2 * j]);
        float bias1 = __ldg(&upd_b1[c0 + 2 * j + 1]);
        #pragma unroll
        for (int i = 0; i < 4; i++) {
            float2 v = upk2(acc[i][j]);
            sA[r0 + i][c0 + 2 * j] = silu_f(v.x + bias0);
            sA[r0 + i][c0 + 2 * j + 1] = silu_f(v.y + bias1);
        }
    }
    __syncthreads();

    u64 asv[4][4], ass[4][4];
    #pragma unroll
    for (int i = 0; i < 4; i++)
        #pragma unroll
        for (int j = 0; j < 4; j++) { asv[i][j] = 0ull; ass[i][j] = 0ull; }

    for (int k0 = 0; k0 < D; k0 += 32) {
        __syncthreads();
        for (int k = t; k < 32 * 64; k += 128) {
            int row = k >> 6, c4 = k & 63;
            *(float4*)(&sW[row][c4 * 4]) = __ldg((const float4*)(upd_W2 + (k0 + row) * 384 + 128 + c4 * 4));
        }
        __syncthreads();
        for (int kk = 0; kk < 32; kk++) {
            u64 ad[4];
            #pragma unroll
            for (int i = 0; i < 4; i++) {
                float a = sA[r0 + i][k0 + kk];
                ad[i] = pk2(a, a);
            }
            ulonglong2 q0 = *(const ulonglong2*)(&sW[kk][c0]);
            ulonglong2 q1 = *(const ulonglong2*)(&sW[kk][c0 + 4]);
            ulonglong2 q2 = *(const ulonglong2*)(&sW[kk][128 + c0]);
            ulonglong2 q3 = *(const ulonglong2*)(&sW[kk][128 + c0 + 4]);
            u64 bsv[4] = {q0.x, q0.y, q1.x, q1.y};
            u64 bss[4] = {q2.x, q2.y, q3.x, q3.y};
            #pragma unroll
            for (int i = 0; i < 4; i++)
                #pragma unroll
                for (int j = 0; j < 4; j++) {
                    fma2(asv[i][j], ad[i], bsv[j]);
                    fma2(ass[i][j], ad[i], bss[j]);
                }
        }
    }

    int base = __ldg(&node_graph_index[0]);
    #pragma unroll
    for (int i = 0; i < 4; i++) {
        int n = n0 + r0 + i;
        if (n < NNODES) {
            int g = __ldg(&node_graph_index[n]) - base;
            float* dst = g_graph + (size_t)g * D + c0;
            float vals[8];
            #pragma unroll
            for (int j = 0; j < 4; j++) {
                float2 sv = upk2(asv[i][j]);
                float2 ss = upk2(ass[i][j]);
                float uv0 = g_UV[(size_t)n * D + c0 + 2 * j];
                float uv1 = g_UV[(size_t)n * D + c0 + 2 * j + 1];
                float a_sv0 = sv.x + __ldg(&upd_b2[D + c0 + 2 * j]);
                float a_sv1 = sv.y + __ldg(&upd_b2[D + c0 + 2 * j + 1]);
                float a_ss0 = ss.x + __ldg(&upd_b2[2 * D + c0 + 2 * j]);
                float a_ss1 = ss.y + __ldg(&upd_b2[2 * D + c0 + 2 * j + 1]);
                vals[2 * j]     = sA[r0 + i][D + c0 + 2 * j]     + uv0 * a_sv0 + a_ss0;
                vals[2 * j + 1] = sA[r0 + i][D + c0 + 2 * j + 1] + uv1 * a_sv1 + a_ss1;
            }
            atomicAdd((float4*)dst,       make_float4(vals[0], vals[1], vals[2], vals[3]));
            atomicAdd((float4*)(dst + 4), make_float4(vals[4], vals[5], vals[6], vals[7]));
        }
    }
}

// ---------------- output MLP: 512 graphs ----------------
__global__ void out_kernel(
    const float* __restrict__ out_W1, const float* __restrict__ out_b1,
    const float* __restrict__ out_W2, const float* __restrict__ out_b2,
    float* __restrict__ out)
{
    __shared__ float sG[D];
    __shared__ float sRed[D];
    const int g = blockIdx.x;
    const int t = threadIdx.x;
    sG[t] = g_graph[(size_t)g * D + t];
    __syncthreads();
    float x = 0.f;
    #pragma unroll 8
    for (int k = 0; k < D; k++) x += sG[k] * __ldg(&out_W1[k * D + t]);
    x += __ldg(&out_b1[t]);
    float p = silu_f(x) * __ldg(&out_W2[t]);
    sRed[t] = p;
    __syncthreads();
    for (int s = 64; s > 0; s >>= 1) {
        if (t < s) sRed[t] += sRed[t + s];
        __syncthreads();
    }
    if (t == 0) out[g] = sRed[0] + __ldg(&out_b2[0]);
}

// ---------------- launch ----------------
extern "C" void kernel_launch(void* const* d_in, const int* in_sizes, int n_in,
                              void* d_out, int out_size)
{
    const float* edge_vec  = (const float*)d_in[0];
    const float* embedding = (const float*)d_in[1];
    const float* phi_W1 = (const float*)d_in[2];
    const float* phi_b1 = (const float*)d_in[3];
    const float* phi_W2 = (const float*)d_in[4];
    const float* phi_b2 = (const float*)d_in[5];
    const float* filt_W = (const float*)d_in[6];
    const float* filt_b = (const float*)d_in[7];
    const float* upd_W1 = (const float*)d_in[8];
    const float* upd_b1 = (const float*)d_in[9];
    const float* upd_W2 = (const float*)d_in[10];
    const float* upd_b2 = (const float*)d_in[11];
    const float* out_W1 = (const float*)d_in[12];
    const float* out_b1 = (const float*)d_in[13];
    const float* out_W2 = (const float*)d_in[14];
    const float* out_b2 = (const float*)d_in[15];
    const float* U_W    = (const float*)d_in[16];
    const float* V_W    = (const float*)d_in[17];
    const int* atom_types = (const int*)d_in[18];
    const int* node_from  = (const int*)d_in[19];
    const int* node_to    = (const int*)d_in[20];
    const int* node_graph_index = (const int*)d_in[21];
    float* out = (float*)d_out;

    init_kernel<<<2048, 256>>>(embedding, atom_types);
    node_phi_kernel<<<(NNODES + 63) / 64, 128>>>(phi_W1, phi_b1, phi_W2, phi_b2);
    edge_kernel<<<(NEDGES + 63) / 64, 256>>>(edge_vec, filt_W, filt_b, node_from, node_to);
    uv_kernel<<<(NNODES + 15) / 16, 256>>>(U_W, V_W);
    update_kernel<<<(NNODES + 31) / 32, 128>>>(upd_W1, upd_b1, upd_W2, upd_b2, node_graph_index);
    out_kernel<<<NGRAPHS, D>>>(out_W1, out_b1, out_W2, out_b2, out);
}

// round 15
// speedup vs baseline: 1.0844x; 1.0844x over previous
#include <cuda_runtime.h>
#include <math.h>

#define D 128
#define NRBF 20
#define NNODES 25000
#define NEDGES 250000
#define NGRAPHS 512

// ---------------- scratch (device globals; no allocation) ----------------
__device__ float g_state0[NNODES * D];
__device__ float g_state_acc[NNODES * D];
__device__ float g_state_vec[NNODES * 3 * D];
__device__ float g_phi[NNODES * 2 * D];         // per-node phi cols 128..383 (m2|m3)
__device__ float g_UV[NNODES * D];
__device__ float g_Vn[NNODES * D];
__device__ float g_graph[NGRAPHS * D];

typedef unsigned long long u64;

__device__ __forceinline__ float silu_f(float x) {
    return x / (1.0f + __expf(-x));
}

__device__ __forceinline__ u64 pk2(float lo, float hi) {
    u64 r;
    asm("mov.b64 %0, {%1, %2};" : "=l"(r) : "r"(__float_as_uint(lo)), "r"(__float_as_uint(hi)));
    return r;
}
__device__ __forceinline__ float2 upk2(u64 v) {
    unsigned lo, hi;
    asm("mov.b64 {%0, %1}, %2;" : "=r"(lo), "=r"(hi) : "l"(v));
    return make_float2(__uint_as_float(lo), __uint_as_float(hi));
}
__device__ __forceinline__ void fma2(u64& acc, u64 a, u64 b) {
    asm("fma.rn.f32x2 %0, %1, %2, %0;" : "+l"(acc) : "l"(a), "l"(b));
}

// ---------------- init ----------------
__global__ void init_kernel(const float* __restrict__ emb, const int* __restrict__ atype) {
    int stride = gridDim.x * blockDim.x;
    int total = NNODES * 3 * D;
    for (int idx = blockIdx.x * blockDim.x + threadIdx.x; idx < total; idx += stride) {
        g_state_vec[idx] = 0.0f;
        if (idx < NNODES * D) {
            int n = idx >> 7;
            int j = idx & 127;
            g_state0[idx] = emb[atype[n] * D + j];
            g_state_acc[idx] = 0.0f;
        }
        if (idx < NGRAPHS * D) g_graph[idx] = 0.0f;
    }
}

// ---------------- per-node phi MLP ----------------
__global__ __launch_bounds__(128) void node_phi_kernel(
    const float* __restrict__ phi_W1, const float* __restrict__ phi_b1,
    const float* __restrict__ phi_W2, const float* __restrict__ phi_b2)
{
    __shared__ float sA[64][132];
    __shared__ float sW[32][132];
    const int t = threadIdx.x;
    const int n0 = blockIdx.x * 64;

    for (int k = t; k < 64 * 32; k += 128) {
        int row = k >> 5, c4 = k & 31;
        int n = n0 + row;
        float4 v = make_float4(0.f, 0.f, 0.f, 0.f);
        if (n < NNODES) v = ((const float4*)(g_state0 + (size_t)n * D))[c4];
        *(float4*)(&sA[row][c4 * 4]) = v;
    }

    const int ty = t >> 4;
    const int tx = t & 15;
    const int r0 = ty * 8, c0 = tx * 8;

    u64 acc[8][4];
    #pragma unroll
    for (int i = 0; i < 8; i++)
        #pragma unroll
        for (int j = 0; j < 4; j++) acc[i][j] = 0ull;

    for (int k0 = 0; k0 < D; k0 += 32) {
        __syncthreads();
        for (int k = t; k < 32 * 32; k += 128) {
            int row = k >> 5, c4 = k & 31;
            *(float4*)(&sW[row][c4 * 4]) = __ldg((const float4*)(phi_W1 + (k0 + row) * D + c4 * 4));
        }
        __syncthreads();
        for (int kk = 0; kk < 32; kk++) {
            u64 ad[8];
            #pragma unroll
            for (int i = 0; i < 8; i++) {
                float a = sA[r0 + i][k0 + kk];
                ad[i] = pk2(a, a);
            }
            ulonglong2 q0 = *(const ulonglong2*)(&sW[kk][c0]);
            ulonglong2 q1 = *(const ulonglong2*)(&sW[kk][c0 + 4]);
            u64 bp[4] = {q0.x, q0.y, q1.x, q1.y};
            #pragma unroll
            for (int i = 0; i < 8; i++)
                #pragma unroll
                for (int j = 0; j < 4; j++) fma2(acc[i][j], ad[i], bp[j]);
        }
    }
    __syncthreads();
    #pragma unroll
    for (int j = 0; j < 4; j++) {
        float bias0 = __ldg(&phi_b1[c0 + 2 * j]);
        float bias1 = __ldg(&phi_b1[c0 + 2 * j + 1]);
        #pragma unroll
        for (int i = 0; i < 8; i++) {
            float2 v = upk2(acc[i][j]);
            sA[r0 + i][c0 + 2 * j] = silu_f(v.x + bias0);
            sA[r0 + i][c0 + 2 * j + 1] = silu_f(v.y + bias1);
        }
    }
    __syncthreads();

    #pragma unroll 1
    for (int half = 0; half < 2; half++) {
        const int cb = D + half * D;
        u64 acc2[8][4];
        #pragma unroll
        for (int i = 0; i < 8; i++)
            #pragma unroll
            for (int j = 0; j < 4; j++) acc2[i][j] = 0ull;

        for (int k0 = 0; k0 < D; k0 += 32) {
            __syncthreads();
            for (int k = t; k < 32 * 32; k += 128) {
                int row = k >> 5, c4 = k & 31;
                *(float4*)(&sW[row][c4 * 4]) = __ldg((const float4*)(phi_W2 + (k0 + row) * 384 + cb + c4 * 4));
            }
            __syncthreads();
            for (int kk = 0; kk < 32; kk++) {
                u64 ad[8];
                #pragma unroll
                for (int i = 0; i < 8; i++) {
                    float a = sA[r0 + i][k0 + kk];
                    ad[i] = pk2(a, a);
                }
                ulonglong2 q0 = *(const ulonglong2*)(&sW[kk][c0]);
                ulonglong2 q1 = *(const ulonglong2*)(&sW[kk][c0 + 4]);
                u64 bp[4] = {q0.x, q0.y, q1.x, q1.y};
                #pragma unroll
                for (int i = 0; i < 8; i++)
                    #pragma unroll
                    for (int j = 0; j < 4; j++) fma2(acc2[i][j], ad[i], bp[j]);
            }
        }

        #pragma unroll
        for (int i = 0; i < 8; i++) {
            int n = n0 + r0 + i;
            if (n < NNODES) {
                float2 p0 = upk2(acc2[i][0]);
                float2 p1 = upk2(acc2[i][1]);
                float2 p2 = upk2(acc2[i][2]);
                float2 p3 = upk2(acc2[i][3]);
                float4* dst = (float4*)(g_phi + (size_t)n * 256 + half * D + c0);
                dst[0] = make_float4(p0.x + __ldg(&phi_b2[cb + c0 + 0]),
                                     p0.y + __ldg(&phi_b2[cb + c0 + 1]),
                                     p1.x + __ldg(&phi_b2[cb + c0 + 2]),
                                     p1.y + __ldg(&phi_b2[cb + c0 + 3]));
                dst[1] = make_float4(p2.x + __ldg(&phi_b2[cb + c0 + 4]),
                                     p2.y + __ldg(&phi_b2[cb + c0 + 5]),
                                     p3.x + __ldg(&phi_b2[cb + c0 + 6]),
                                     p3.y + __ldg(&phi_b2[cb + c0 + 7]));
            }
        }
    }
}

// ---------------- edge kernel: smem-staged filter GEMM + gather + scatter ----------------
// 64 edges / block, 256 threads. Warp-uniform scatter mapping:
//   half = t>>7 (warps 0-3 -> m2 cols 0..127, warps 4-7 -> m3 cols 128..255)
//   es   = (t>>4)&7  (edge slot; 2 slots per warp)
//   c0   = half*128 + (t&15)*8
__global__ __launch_bounds__(256) void edge_kernel(
    const float* __restrict__ edge_vec,
    const float* __restrict__ filt_W, const float* __restrict__ filt_b,
    const int* __restrict__ node_from, const int* __restrict__ node_to)
{
    __shared__ float sW[20][264];
    __shared__ float sWb[256];
    __shared__ float sRbf[64][22];
    __shared__ float sFc[64];
    __shared__ float sFcInv[64];
    __shared__ float sDist[64];
    __shared__ float sNorm[64][4];
    __shared__ int   sFrom[64];
    __shared__ int   sTo[64];

    const int t = threadIdx.x;
    const int e0 = blockIdx.x * 64;
    const float PI = 3.14159265358979323846f;

    for (int k = t; k < 20 * 64; k += 256) {
        int row = k >> 6, c4 = k & 63;
        *(float4*)(&sW[row][c4 * 4]) = __ldg((const float4*)(filt_W + row * 384 + 128 + c4 * 4));
    }
    if (t < 64) *(float4*)(&sWb[t * 4]) = __ldg((const float4*)(filt_b + 128 + t * 4));

    if (t < 64) {
        int e = e0 + t;
        float d = 1.f, fcv = 0.f, nx = 0.f, ny = 0.f, nz = 0.f;
        int f = 0, to = 0;
        if (e < NEDGES) {
            float x = edge_vec[3 * e + 0];
            float y = edge_vec[3 * e + 1];
            float z = edge_vec[3 * e + 2];
            d = sqrtf(x * x + y * y + z * z);
            float inv = 1.0f / d;
            fcv = (d < 10.0f) ? 0.5f * (__cosf(PI * d * 0.1f) + 1.0f) : 0.0f;
            nx = x * inv; ny = y * inv; nz = z * inv;
            f = node_from[e]; to = node_to[e];
        }
        sDist[t] = d;
        sFc[t] = fcv;
        sFcInv[t] = fcv / d;
        sNorm[t][0] = nx; sNorm[t][1] = ny; sNorm[t][2] = nz;
        sFrom[t] = f; sTo[t] = to;
    }
    __syncthreads();
    for (int idx = t; idx < 64 * NRBF; idx += 256) {
        int le = idx & 63;
        int r = idx >> 6;
        sRbf[le][r] = __sinf((float)(r + 1) * PI * sDist[le] * 0.1f) * sFcInv[le];
    }
    __syncthreads();

    const int half = t >> 7;                 // 0: m2 cols, 1: m3 cols (warp-uniform)
    const int es = (t >> 4) & 7;             // edge slot
    const int c0 = half * 128 + (t & 15) * 8;

    ulonglong2 qb0 = *(const ulonglong2*)(&sWb[c0]);
    ulonglong2 qb1 = *(const ulonglong2*)(&sWb[c0 + 4]);
    u64 wb[4] = {qb0.x, qb0.y, qb1.x, qb1.y};

    u64 acc[8][4];
    #pragma unroll
    for (int m = 0; m < 8; m++) {
        float fc = sFc[es + 8 * m];
        u64 fp = pk2(fc, fc);
        #pragma unroll
        for (int j = 0; j < 4; j++) {
            acc[m][j] = 0ull;
            fma2(acc[m][j], fp, wb[j]);
        }
    }

    // filter GEMM: W_out = rbf_fc @ filt_W + fc*b  (8 edges per thread)
    #pragma unroll
    for (int r = 0; r < NRBF; r++) {
        ulonglong2 q0 = *(const ulonglong2*)(&sW[r][c0]);
        ulonglong2 q1 = *(const ulonglong2*)(&sW[r][c0 + 4]);
        u64 b[4] = {q0.x, q0.y, q1.x, q1.y};
        #pragma unroll
        for (int m = 0; m < 8; m++) {
            float a = sRbf[es + 8 * m][r];
            u64 av = pk2(a, a);
            #pragma unroll
            for (int j = 0; j < 4; j++) fma2(acc[m][j], av, b[j]);
        }
    }

    if (half == 0) {
        // m2 -> state accumulator
        #pragma unroll 1
        for (int m = 0; m < 8; m++) {
            int le = es + 8 * m;
            int e = e0 + le;
            if (e >= NEDGES) continue;
            const float4* ph = (const float4*)(g_phi + (size_t)sFrom[le] * 256 + c0);
            float4 p0 = ph[0];
            float4 p1 = ph[1];
            float2 w0 = upk2(acc[m][0]);
            float2 w1 = upk2(acc[m][1]);
            float2 w2 = upk2(acc[m][2]);
            float2 w3 = upk2(acc[m][3]);
            float4* dst = (float4*)(g_state_acc + (size_t)sTo[le] * D + c0);
            atomicAdd(dst,     make_float4(p0.x * w0.x, p0.y * w0.y, p0.z * w1.x, p0.w * w1.y));
            atomicAdd(dst + 1, make_float4(p1.x * w2.x, p1.y * w2.y, p1.z * w3.x, p1.w * w3.y));
        }
    } else {
        // m3 -> msg_vec = normalized * m3
        #pragma unroll 1
        for (int m = 0; m < 8; m++) {
            int le = es + 8 * m;
            int e = e0 + le;
            if (e >= NEDGES) continue;
            const float4* ph = (const float4*)(g_phi + (size_t)sFrom[le] * 256 + c0);
            float4 p0 = ph[0];
            float4 p1 = ph[1];
            float2 w0 = upk2(acc[m][0]);
            float2 w1 = upk2(acc[m][1]);
            float2 w2 = upk2(acc[m][2]);
            float2 w3 = upk2(acc[m][3]);
            float pf[8];
            pf[0] = p0.x * w0.x; pf[1] = p0.y * w0.y; pf[2] = p0.z * w1.x; pf[3] = p0.w * w1.y;
            pf[4] = p1.x * w2.x; pf[5] = p1.y * w2.y; pf[6] = p1.z * w3.x; pf[7] = p1.w * w3.y;
            const int jj = c0 - 128;
            float n0 = sNorm[le][0], n1 = sNorm[le][1], n2 = sNorm[le][2];
            float* base = g_state_vec + (size_t)sTo[le] * (3 * D) + jj;
            atomicAdd((float4*)(base),             make_float4(n0 * pf[0], n0 * pf[1], n0 * pf[2], n0 * pf[3]));
            atomicAdd((float4*)(base + 4),         make_float4(n0 * pf[4], n0 * pf[5], n0 * pf[6], n0 * pf[7]));
            atomicAdd((float4*)(base + D),         make_float4(n1 * pf[0], n1 * pf[1], n1 * pf[2], n1 * pf[3]));
            atomicAdd((float4*)(base + D + 4),     make_float4(n1 * pf[4], n1 * pf[5], n1 * pf[6], n1 * pf[7]));
            atomicAdd((float4*)(base + 2 * D),     make_float4(n2 * pf[0], n2 * pf[1], n2 * pf[2], n2 * pf[3]));
            atomicAdd((float4*)(base + 2 * D + 4), make_float4(n2 * pf[4], n2 * pf[5], n2 * pf[6], n2 * pf[7]));
        }
    }
}

// ---------------- fused UV kernel: Up/Vp GEMM + UV/Vn reduce (R10 proven) ----------------
__global__ __launch_bounds__(256, 3) void uv_kernel(
    const float* __restrict__ U_W, const float* __restrict__ V_W)
{
    __shared__ float sAt[16][68];
    __shared__ float sU[16][132];
    __shared__ float sV[16][132];
    const int t = threadIdx.x;
    const int nb0 = blockIdx.x * 16;
    const int rb = nb0 * 3;
    const int NR = NNODES * 3;

    const int ng = t >> 5;
    const int c0 = (t & 31) * 4;

    u64 acc_u[2][3][2], acc_v[2][3][2];
    #pragma unroll
    for (int m = 0; m < 2; m++)
        #pragma unroll
        for (int c = 0; c < 3; c++)
            #pragma unroll
            for (int j = 0; j < 2; j++) { acc_u[m][c][j] = 0ull; acc_v[m][c][j] = 0ull; }

    for (int k0 = 0; k0 < D; k0 += 16) {
        __syncthreads();
        for (int idx = t; idx < 48 * 16; idx += 256) {
            int row = idx >> 4;
            int k = idx & 15;
            int r = rb + row;
            float v = (r < NR) ? g_state_vec[(size_t)r * D + k0 + k] : 0.f;
            int nl = row / 3, comp = row - nl * 3;
            sAt[k][nl * 4 + comp] = v;
        }
        for (int k = t; k < 16 * 32; k += 256) {
            int row = k >> 5, c4 = k & 31;
            *(float4*)(&sU[row][c4 * 4]) = __ldg((const float4*)(U_W + (k0 + row) * D + c4 * 4));
            *(float4*)(&sV[row][c4 * 4]) = __ldg((const float4*)(V_W + (k0 + row) * D + c4 * 4));
        }
        __syncthreads();
        #pragma unroll
        for (int kk = 0; kk < 16; kk++) {
            ulonglong2 qu = *(const ulonglong2*)(&sU[kk][c0]);
            ulonglong2 qv = *(const ulonglong2*)(&sV[kk][c0]);
            u64 bu[2] = {qu.x, qu.y};
            u64 bv[2] = {qv.x, qv.y};
            #pragma unroll
            for (int m = 0; m < 2; m++) {
                float4 a = *(const float4*)(&sAt[kk][(ng + 8 * m) * 4]);
                u64 d0 = pk2(a.x, a.x), d1 = pk2(a.y, a.y), d2 = pk2(a.z, a.z);
                #pragma unroll
                for (int j = 0; j < 2; j++) {
                    fma2(acc_u[m][0][j], d0, bu[j]);
                    fma2(acc_u[m][1][j], d1, bu[j]);
                    fma2(acc_u[m][2][j], d2, bu[j]);
                    fma2(acc_v[m][0][j], d0, bv[j]);
                    fma2(acc_v[m][1][j], d1, bv[j]);
                    fma2(acc_v[m][2][j], d2, bv[j]);
                }
            }
        }
    }

    #pragma unroll
    for (int m = 0; m < 2; m++) {
        int node = nb0 + ng + 8 * m;
        if (node < NNODES) {
            float uvv[4], vnv[4];
            #pragma unroll
            for (int j = 0; j < 2; j++) {
                float2 U0 = upk2(acc_u[m][0][j]), U1 = upk2(acc_u[m][1][j]), U2 = upk2(acc_u[m][2][j]);
                float2 V0 = upk2(acc_v[m][0][j]), V1 = upk2(acc_v[m][1][j]), V2 = upk2(acc_v[m][2][j]);
                uvv[2 * j]     = U0.x * V0.x + U1.x * V1.x + U2.x * V2.x;
                uvv[2 * j + 1] = U0.y * V0.y + U1.y * V1.y + U2.y * V2.y;
                vnv[2 * j]     = sqrtf(V0.x * V0.x + V1.x * V1.x + V2.x * V2.x);
                vnv[2 * j + 1] = sqrtf(V0.y * V0.y + V1.y * V1.y + V2.y * V2.y);
            }
            *(float4*)(g_UV + (size_t)node * D + c0) = make_float4(uvv[0], uvv[1], uvv[2], uvv[3]);
            *(float4*)(g_Vn + (size_t)node * D + c0) = make_float4(vnv[0], vnv[1], vnv[2], vnv[3]);
        }
    }
}

// ---------------- node update MLP + segment-sum (R8 proven version) ----------------
__global__ __launch_bounds__(128) void update_kernel(
    const float* __restrict__ upd_W1, const float* __restrict__ upd_b1,
    const float* __restrict__ upd_W2, const float* __restrict__ upd_b2,
    const int* __restrict__ node_graph_index)
{
    __shared__ float sA[32][260];
    __shared__ float sW[32][264];
    const int t = threadIdx.x;
    const int n0 = blockIdx.x * 32;

    for (int k = t; k < 32 * 64; k += 128) {
        int row = k >> 6, c4 = k & 63;
        int n = n0 + row;
        float4 v = make_float4(0.f, 0.f, 0.f, 0.f);
        if (n < NNODES) {
            if (c4 < 32) {
                v = ((const float4*)(g_Vn + (size_t)n * D))[c4];
            } else {
                float4 s0 = ((const float4*)(g_state0 + (size_t)n * D))[c4 - 32];
                float4 s1 = ((const float4*)(g_state_acc + (size_t)n * D))[c4 - 32];
                v = make_float4(s0.x + s1.x, s0.y + s1.y, s0.z + s1.z, s0.w + s1.w);
            }
        }
        *(float4*)(&sA[row][c4 * 4]) = v;
    }

    const int ty = t >> 4;
    const int tx = t & 15;
    const int r0 = ty * 4, c0 = tx * 8;

    u64 acc[4][4];
    #pragma unroll
    for (int i = 0; i < 4; i++)
        #pragma unroll
        for (int j = 0; j < 4; j++) acc[i][j] = 0ull;

    for (int k0 = 0; k0 < 2 * D; k0 += 32) {
        __syncthreads();
        for (int k = t; k < 32 * 32; k += 128) {
            int row = k >> 5, c4 = k & 31;
            *(float4*)(&sW[row][c4 * 4]) = __ldg((const float4*)(upd_W1 + (k0 + row) * D + c4 * 4));
        }
        __syncthreads();
        for (int kk = 0; kk < 32; kk++) {
            u64 ad[4];
            #pragma unroll
            for (int i = 0; i < 4; i++) {
                float a = sA[r0 + i][k0 + kk];
                ad[i] = pk2(a, a);
            }
            ulonglong2 q0 = *(const ulonglong2*)(&sW[kk][c0]);
            ulonglong2 q1 = *(const ulonglong2*)(&sW[kk][c0 + 4]);
            u64 bp[4] = {q0.x, q0.y, q1.x, q1.y};
            #pragma unroll
            for (int i = 0; i < 4; i++)
                #pragma unroll
                for (int j = 0; j < 4; j++) fma2(acc[i][j], ad[i], bp[j]);
        }
    }
    __syncthreads();
    #pragma unroll
    for (int j = 0; j < 4; j++) {
        float bias0 = __ldg(&upd_b1[c0 + 2 * j]);
        float bias1 = __ldg(&upd_b1[c0 + 2 * j + 1]);
        #pragma unroll
        for (int i = 0; i < 4; i++) {
            float2 v = upk2(acc[i][j]);
            sA[r0 + i][c0 + 2 * j] = silu_f(v.x + bias0);
            sA[r0 + i][c0 + 2 * j + 1] = silu_f(v.y + bias1);
        }
    }
    __syncthreads();

    u64 asv[4][4], ass[4][4];
    #pragma unroll
    for (int i = 0; i < 4; i++)
        #pragma unroll
        for (int j = 0; j < 4; j++) { asv[i][j] = 0ull; ass[i][j] = 0ull; }

    for (int k0 = 0; k0 < D; k0 += 32) {
        __syncthreads();
        for (int k = t; k < 32 * 64; k += 128) {
            int row = k >> 6, c4 = k & 63;
            *(float4*)(&sW[row][c4 * 4]) = __ldg((const float4*)(upd_W2 + (k0 + row) * 384 + 128 + c4 * 4));
        }
        __syncthreads();
        for (int kk = 0; kk < 32; kk++) {
            u64 ad[4];
            #pragma unroll
            for (int i = 0; i < 4; i++) {
                float a = sA[r0 + i][k0 + kk];
                ad[i] = pk2(a, a);
            }
            ulonglong2 q0 = *(const ulonglong2*)(&sW[kk][c0]);
            ulonglong2 q1 = *(const ulonglong2*)(&sW[kk][c0 + 4]);
            ulonglong2 q2 = *(const ulonglong2*)(&sW[kk][128 + c0]);
            ulonglong2 q3 = *(const ulonglong2*)(&sW[kk][128 + c0 + 4]);
            u64 bsv[4] = {q0.x, q0.y, q1.x, q1.y};
            u64 bss[4] = {q2.x, q2.y, q3.x, q3.y};
            #pragma unroll
            for (int i = 0; i < 4; i++)
                #pragma unroll
                for (int j = 0; j < 4; j++) {
                    fma2(asv[i][j], ad[i], bsv[j]);
                    fma2(ass[i][j], ad[i], bss[j]);
                }
        }
    }

    int base = __ldg(&node_graph_index[0]);
    #pragma unroll
    for (int i = 0; i < 4; i++) {
        int n = n0 + r0 + i;
        if (n < NNODES) {
            int g = __ldg(&node_graph_index[n]) - base;
            float* dst = g_graph + (size_t)g * D + c0;
            float vals[8];
            #pragma unroll
            for (int j = 0; j < 4; j++) {
                float2 sv = upk2(asv[i][j]);
                float2 ss = upk2(ass[i][j]);
                float uv0 = g_UV[(size_t)n * D + c0 + 2 * j];
                float uv1 = g_UV[(size_t)n * D + c0 + 2 * j + 1];
                float a_sv0 = sv.x + __ldg(&upd_b2[D + c0 + 2 * j]);
                float a_sv1 = sv.y + __ldg(&upd_b2[D + c0 + 2 * j + 1]);
                float a_ss0 = ss.x + __ldg(&upd_b2[2 * D + c0 + 2 * j]);
                float a_ss1 = ss.y + __ldg(&upd_b2[2 * D + c0 + 2 * j + 1]);
                vals[2 * j]     = sA[r0 + i][D + c0 + 2 * j]     + uv0 * a_sv0 + a_ss0;
                vals[2 * j + 1] = sA[r0 + i][D + c0 + 2 * j + 1] + uv1 * a_sv1 + a_ss1;
            }
            atomicAdd((float4*)dst,       make_float4(vals[0], vals[1], vals[2], vals[3]));
            atomicAdd((float4*)(dst + 4), make_float4(vals[4], vals[5], vals[6], vals[7]));
        }
    }
}

// ---------------- output MLP: 512 graphs ----------------
__global__ void out_kernel(
    const float* __restrict__ out_W1, const float* __restrict__ out_b1,
    const float* __restrict__ out_W2, const float* __restrict__ out_b2,
    float* __restrict__ out)
{
    __shared__ float sG[D];
    __shared__ float sRed[D];
    const int g = blockIdx.x;
    const int t = threadIdx.x;
    sG[t] = g_graph[(size_t)g * D + t];
    __syncthreads();
    float x = 0.f;
    #pragma unroll 8
    for (int k = 0; k < D; k++) x += sG[k] * __ldg(&out_W1[k * D + t]);
    x += __ldg(&out_b1[t]);
    float p = silu_f(x) * __ldg(&out_W2[t]);
    sRed[t] = p;
    __syncthreads();
    for (int s = 64; s > 0; s >>= 1) {
        if (t < s) sRed[t] += sRed[t + s];
        __syncthreads();
    }
    if (t == 0) out[g] = sRed[0] + __ldg(&out_b2[0]);
}

// ---------------- launch ----------------
extern "C" void kernel_launch(void* const* d_in, const int* in_sizes, int n_in,
                              void* d_out, int out_size)
{
    const float* edge_vec  = (const float*)d_in[0];
    const float* embedding = (const float*)d_in[1];
    const float* phi_W1 = (const float*)d_in[2];
    const float* phi_b1 = (const float*)d_in[3];
    const float* phi_W2 = (const float*)d_in[4];
    const float* phi_b2 = (const float*)d_in[5];
    const float* filt_W = (const float*)d_in[6];
    const float* filt_b = (const float*)d_in[7];
    const float* upd_W1 = (const float*)d_in[8];
    const float* upd_b1 = (const float*)d_in[9];
    const float* upd_W2 = (const float*)d_in[10];
    const float* upd_b2 = (const float*)d_in[11];
    const float* out_W1 = (const float*)d_in[12];
    const float* out_b1 = (const float*)d_in[13];
    const float* out_W2 = (const float*)d_in[14];
    const float* out_b2 = (const float*)d_in[15];
    const float* U_W    = (const float*)d_in[16];
    const float* V_W    = (const float*)d_in[17];
    const int* atom_types = (const int*)d_in[18];
    const int* node_from  = (const int*)d_in[19];
    const int* node_to    = (const int*)d_in[20];
    const int* node_graph_index = (const int*)d_in[21];
    float* out = (float*)d_out;

    init_kernel<<<2048, 256>>>(embedding, atom_types);
    node_phi_kernel<<<(NNODES + 63) / 64, 128>>>(phi_W1, phi_b1, phi_W2, phi_b2);
    edge_kernel<<<(NEDGES + 63) / 64, 256>>>(edge_vec, filt_W, filt_b, node_from, node_to);
    uv_kernel<<<(NNODES + 15) / 16, 256>>>(U_W, V_W);
    update_kernel<<<(NNODES + 31) / 32, 128>>>(upd_W1, upd_b1, upd_W2, upd_b2, node_graph_index);
    out_kernel<<<NGRAPHS, D>>>(out_W1, out_b1, out_W2, out_b2, out);
}